// round 1
// baseline (speedup 1.0000x reference)
#include <cuda_runtime.h>
#include <cuda_bf16.h>
#include <cstddef>

// ---------------------------------------------------------------------------
// CrossAttention: B=16, N=256, T=4096, D=1024, HEADS=8, DIM_HEAD=128
// Inputs  : img_queries(16,256,1024) x(16,4096,1024) gamma_q(1024)
//           gamma_x(1024) W_kv(1024,256)
// Outputs : out(16, 256*8*1024)  then  attn(16,8,256,4096)   (concat in d_out)
// ---------------------------------------------------------------------------

#define B_    16
#define N_    256
#define T_    4096
#define D_    1024
#define H_    8
#define DH_   128

// scratch (allocation-free rule: __device__ globals)
__device__ float g_xn[B_ * T_ * D_];        // 268 MB: layernormed x
__device__ float g_qn[B_ * N_ * D_];        // 16.8 MB: layernormed q (pre-scaled)
__device__ float g_k [B_ * T_ * DH_];       // 33.5 MB: k = x_n @ W_kv[:, :128]

static const size_t OUT_ELEMS  = (size_t)B_ * N_ * H_ * D_;       // 33,554,432
// attn region follows out in d_out

// ---------------------------------------------------------------------------
// reductions
// ---------------------------------------------------------------------------
__device__ __forceinline__ float warpSum(float v) {
#pragma unroll
  for (int o = 16; o > 0; o >>= 1) v += __shfl_xor_sync(0xffffffffu, v, o);
  return v;
}
__device__ __forceinline__ float warpMax(float v) {
#pragma unroll
  for (int o = 16; o > 0; o >>= 1) v = fmaxf(v, __shfl_xor_sync(0xffffffffu, v, o));
  return v;
}

// ---------------------------------------------------------------------------
// LayerNorm: one block (256 thr) per row of 1024 floats.
// which==0 -> write g_xn ; which==1 -> write g_qn (with postScale folded in)
// ---------------------------------------------------------------------------
__global__ __launch_bounds__(256) void ln_kernel(const float* __restrict__ in,
                                                 const float* __restrict__ gamma,
                                                 float postScale, int which) {
  __shared__ float redS[8];
  __shared__ float redQ[8];
  float* outBase = which ? g_qn : g_xn;

  size_t row = blockIdx.x;
  int t = threadIdx.x;
  const float4* p = (const float4*)(in + row * D_);
  float4 v = p[t];

  float s = v.x + v.y + v.z + v.w;
  float q = v.x * v.x + v.y * v.y + v.z * v.z + v.w * v.w;
  s = warpSum(s);
  q = warpSum(q);
  int w = t >> 5, l = t & 31;
  if (l == 0) { redS[w] = s; redQ[w] = q; }
  __syncthreads();
  if (t < 32) {
    float a = (l < 8) ? redS[l] : 0.0f;
    float b = (l < 8) ? redQ[l] : 0.0f;
    a = warpSum(a);
    b = warpSum(b);
    if (l == 0) { redS[0] = a; redQ[0] = b; }
  }
  __syncthreads();
  float mean = redS[0] * (1.0f / (float)D_);
  float var  = redQ[0] * (1.0f / (float)D_) - mean * mean;
  float rstd = rsqrtf(var + 1e-5f) * postScale;

  float4 g = ((const float4*)gamma)[t];
  float4 o;
  o.x = (v.x - mean) * rstd * g.x;
  o.y = (v.y - mean) * rstd * g.y;
  o.z = (v.z - mean) * rstd * g.z;
  o.w = (v.w - mean) * rstd * g.w;
  ((float4*)(outBase + row * D_))[t] = o;
}

// ---------------------------------------------------------------------------
// Softmax over rows of 4096, in place (attn region of d_out).
// One block (256 thr) per row; 16 floats per thread held in registers.
// ---------------------------------------------------------------------------
__global__ __launch_bounds__(256) void softmax_kernel(float* __restrict__ attn) {
  __shared__ float red[8];
  size_t row = blockIdx.x;
  int t = threadIdx.x;
  float4* p = (float4*)(attn + row * (size_t)T_);

  float4 v[4];
#pragma unroll
  for (int i = 0; i < 4; i++) v[i] = p[t + i * 256];

  float m = -3.4e38f;
#pragma unroll
  for (int i = 0; i < 4; i++)
    m = fmaxf(m, fmaxf(fmaxf(v[i].x, v[i].y), fmaxf(v[i].z, v[i].w)));
  m = warpMax(m);
  int w = t >> 5, l = t & 31;
  if (l == 0) red[w] = m;
  __syncthreads();
  if (t < 32) {
    float a = (l < 8) ? red[l] : -3.4e38f;
    a = warpMax(a);
    if (l == 0) red[0] = a;
  }
  __syncthreads();
  m = red[0];
  __syncthreads();

  float s = 0.0f;
#pragma unroll
  for (int i = 0; i < 4; i++) {
    v[i].x = __expf(v[i].x - m);
    v[i].y = __expf(v[i].y - m);
    v[i].z = __expf(v[i].z - m);
    v[i].w = __expf(v[i].w - m);
    s += v[i].x + v[i].y + v[i].z + v[i].w;
  }
  s = warpSum(s);
  if (l == 0) red[w] = s;
  __syncthreads();
  if (t < 32) {
    float a = (l < 8) ? red[l] : 0.0f;
    a = warpSum(a);
    if (l == 0) red[0] = a;
  }
  __syncthreads();
  float inv = 1.0f / red[0];
#pragma unroll
  for (int i = 0; i < 4; i++) {
    v[i].x *= inv; v[i].y *= inv; v[i].z *= inv; v[i].w *= inv;
    p[t + i * 256] = v[i];
  }
}

// ---------------------------------------------------------------------------
// Tiled SGEMM: 128x128 block tile, BK=16, 256 threads, 8x8 per thread.
// MODE 0: g_k[m,n] = g_xn[m,:] @ W_kv[:, n]        (M=65536, N=128, K=1024, NN)
// MODE 1: sim      = g_qn_tile @ g_k_tile^T        (per-b M=2048, N=4096, K=128, NT)
// MODE 2: out      = attn_tile @ g_xn_tile         (per-bh M=256, N=1024, K=4096, NN)
// All tile dims divide exactly -> no bounds checks.
// ---------------------------------------------------------------------------
#define BM 128
#define BN 128
#define BK 16
#define TM 8
#define TN 8

template <int MODE>
__global__ __launch_bounds__(256) void gemm_kernel(const float* __restrict__ P0,
                                                   float* __restrict__ P1) {
  const float* A;
  const float* Bm;
  float* C;
  int lda, ldb, ldc, K;
  constexpr bool BT = (MODE == 1);

  if constexpr (MODE == 0) {
    // grid (1, 512)
    A   = g_xn + (size_t)blockIdx.y * BM * D_;  lda = D_;
    Bm  = P0;                                   ldb = 256;   // W_kv, use cols [0,128)
    C   = g_k + (size_t)blockIdx.y * BM * DH_;  ldc = DH_;
    K   = D_;
  } else if constexpr (MODE == 1) {
    // grid (32, 16, 16): bx = key tile, by = m tile (m = h*256+i), bz = batch
    int b = blockIdx.z, by = blockIdx.y, bx = blockIdx.x;
    int h = by >> 1;
    int i0 = (by & 1) * BM;
    A   = g_qn + (size_t)b * (N_ * D_) + (size_t)i0 * D_ + h * DH_;  lda = D_;
    Bm  = g_k  + (size_t)b * (T_ * DH_) + (size_t)bx * BM * DH_;     ldb = DH_; // N-major
    C   = P1 + ((size_t)b * 2048 + (size_t)by * BM) * T_ + (size_t)bx * BN;
    ldc = T_;
    K   = DH_;
  } else {
    // grid (8, 2, 128): bz = b*8+h
    int bz = blockIdx.z, by = blockIdx.y, bx = blockIdx.x;
    int b = bz >> 3, h = bz & 7;
    A   = P0 + ((size_t)bz * N_ + (size_t)by * BM) * T_;             lda = T_;
    Bm  = g_xn + (size_t)b * (T_ * D_) + (size_t)bx * BN;            ldb = D_;
    C   = P1 + (size_t)b * (N_ * H_ * D_) + (size_t)by * BM * (H_ * D_)
             + (size_t)h * D_ + (size_t)bx * BN;
    ldc = H_ * D_;   // 8192
    K   = T_;
  }

  __shared__ float As[BK][BM];
  __shared__ float Bs[BK][BN];

  int tid = threadIdx.x;
  int tx = tid & 15, ty = tid >> 4;

  float acc[TM][TN];
#pragma unroll
  for (int r = 0; r < TM; r++)
#pragma unroll
    for (int c = 0; c < TN; c++) acc[r][c] = 0.0f;

  // A-tile loader indices (also used for transposed B in NT mode)
  const int ar = tid >> 1;           // row 0..127
  const int ac = (tid & 1) * 8;      // k offset 0 or 8
  // B-tile loader indices (NN mode)
  const int bnr = tid >> 4;          // k row 0..15
  const int bnc = (tid & 15) * 4;    // col 0..60

  for (int kt = 0; kt < K; kt += BK) {
    {
      float4 a0 = *(const float4*)(A + (size_t)ar * lda + kt + ac);
      float4 a1 = *(const float4*)(A + (size_t)ar * lda + kt + ac + 4);
      As[ac + 0][ar] = a0.x; As[ac + 1][ar] = a0.y;
      As[ac + 2][ar] = a0.z; As[ac + 3][ar] = a0.w;
      As[ac + 4][ar] = a1.x; As[ac + 5][ar] = a1.y;
      As[ac + 6][ar] = a1.z; As[ac + 7][ar] = a1.w;
    }
    if constexpr (!BT) {
      float4 b0 = *(const float4*)(Bm + (size_t)(kt + bnr) * ldb + bnc);
      float4 b1 = *(const float4*)(Bm + (size_t)(kt + bnr) * ldb + bnc + 64);
      *(float4*)&Bs[bnr][bnc]      = b0;
      *(float4*)&Bs[bnr][bnc + 64] = b1;
    } else {
      float4 b0 = *(const float4*)(Bm + (size_t)ar * ldb + kt + ac);
      float4 b1 = *(const float4*)(Bm + (size_t)ar * ldb + kt + ac + 4);
      Bs[ac + 0][ar] = b0.x; Bs[ac + 1][ar] = b0.y;
      Bs[ac + 2][ar] = b0.z; Bs[ac + 3][ar] = b0.w;
      Bs[ac + 4][ar] = b1.x; Bs[ac + 5][ar] = b1.y;
      Bs[ac + 6][ar] = b1.z; Bs[ac + 7][ar] = b1.w;
    }
    __syncthreads();

#pragma unroll
    for (int kk = 0; kk < BK; kk++) {
      float a[TM], b[TN];
      *(float4*)&a[0] = *(const float4*)&As[kk][ty * TM];
      *(float4*)&a[4] = *(const float4*)&As[kk][ty * TM + 4];
      *(float4*)&b[0] = *(const float4*)&Bs[kk][tx * TN];
      *(float4*)&b[4] = *(const float4*)&Bs[kk][tx * TN + 4];
#pragma unroll
      for (int r = 0; r < TM; r++)
#pragma unroll
        for (int c = 0; c < TN; c++) acc[r][c] += a[r] * b[c];
    }
    __syncthreads();
  }

#pragma unroll
  for (int r = 0; r < TM; r++) {
    float* crow = C + (size_t)(ty * TM + r) * ldc + tx * TN;
    *(float4*)crow       = make_float4(acc[r][0], acc[r][1], acc[r][2], acc[r][3]);
    *(float4*)(crow + 4) = make_float4(acc[r][4], acc[r][5], acc[r][6], acc[r][7]);
  }
}

// ---------------------------------------------------------------------------
// launch
// ---------------------------------------------------------------------------
extern "C" void kernel_launch(void* const* d_in, const int* in_sizes, int n_in,
                              void* d_out, int out_size) {
  (void)in_sizes; (void)n_in; (void)out_size;
  const float* imgq = (const float*)d_in[0];   // (16,256,1024)
  const float* x    = (const float*)d_in[1];   // (16,4096,1024)
  const float* gq   = (const float*)d_in[2];   // (1024,)
  const float* gx   = (const float*)d_in[3];   // (1024,)
  const float* wkv  = (const float*)d_in[4];   // (1024,256)

  float* out  = (float*)d_out;
  float* attn = out + OUT_ELEMS;

  const float scale = 0.08838834764831845f;    // DIM_HEAD^-0.5

  // 1. layernorms
  ln_kernel<<<B_ * T_, 256>>>(x, gx, 1.0f, 0);       // -> g_xn
  ln_kernel<<<B_ * N_, 256>>>(imgq, gq, scale, 1);   // -> g_qn (pre-scaled)

  // 2. k = x_n @ W_kv[:, :128]   (v is never used by the reference)
  gemm_kernel<0><<<dim3(1, 512), 256>>>(wkv, nullptr);

  // 3. sim -> attn region (raw scores)
  gemm_kernel<1><<<dim3(32, 16, 16), 256>>>(nullptr, attn);

  // 4. softmax in place
  softmax_kernel<<<B_ * H_ * N_, 256>>>(attn);

  // 5. out = attn @ x_n
  gemm_kernel<2><<<dim3(8, 2, 128), 256>>>(attn, out);
}

// round 11
// speedup vs baseline: 2.5893x; 2.5893x over previous
#include <cuda_runtime.h>
#include <cuda_bf16.h>
#include <cstddef>
#include <cstdint>

// ---------------------------------------------------------------------------
// CrossAttention: B=16, N=256, T=4096, D=1024, HEADS=8, DIM_HEAD=128
// out(16, 256*8*1024) ++ attn(16,8,256,4096) in d_out
// R4 (resubmit x7): out-GEMM AND sim-GEMM on tensor pipe (mma.sync tf32, rna).
// ---------------------------------------------------------------------------

#define B_    16
#define N_    256
#define T_    4096
#define D_    1024
#define H_    8
#define DH_   128

__device__ float g_xn[B_ * T_ * D_];
__device__ float g_qn[B_ * N_ * D_];
__device__ float g_k [B_ * T_ * DH_];

static const size_t OUT_ELEMS = (size_t)B_ * N_ * H_ * D_;

// ---------------------------------------------------------------------------
__device__ __forceinline__ float warpSum(float v) {
#pragma unroll
  for (int o = 16; o > 0; o >>= 1) v += __shfl_xor_sync(0xffffffffu, v, o);
  return v;
}
__device__ __forceinline__ float warpMax(float v) {
#pragma unroll
  for (int o = 16; o > 0; o >>= 1) v = fmaxf(v, __shfl_xor_sync(0xffffffffu, v, o));
  return v;
}

// ---------------------------------------------------------------------------
__global__ __launch_bounds__(256) void ln_kernel(const float* __restrict__ in,
                                                 const float* __restrict__ gamma,
                                                 float postScale, int which) {
  __shared__ float redS[8];
  __shared__ float redQ[8];
  float* outBase = which ? g_qn : g_xn;

  size_t row = blockIdx.x;
  int t = threadIdx.x;
  const float4* p = (const float4*)(in + row * D_);
  float4 v = p[t];

  float s = v.x + v.y + v.z + v.w;
  float q = v.x * v.x + v.y * v.y + v.z * v.z + v.w * v.w;
  s = warpSum(s);
  q = warpSum(q);
  int w = t >> 5, l = t & 31;
  if (l == 0) { redS[w] = s; redQ[w] = q; }
  __syncthreads();
  if (t < 32) {
    float a = (l < 8) ? redS[l] : 0.0f;
    float b = (l < 8) ? redQ[l] : 0.0f;
    a = warpSum(a);
    b = warpSum(b);
    if (l == 0) { redS[0] = a; redQ[0] = b; }
  }
  __syncthreads();
  float mean = redS[0] * (1.0f / (float)D_);
  float var  = redQ[0] * (1.0f / (float)D_) - mean * mean;
  float rstd = rsqrtf(var + 1e-5f) * postScale;

  float4 g = ((const float4*)gamma)[t];
  float4 o;
  o.x = (v.x - mean) * rstd * g.x;
  o.y = (v.y - mean) * rstd * g.y;
  o.z = (v.z - mean) * rstd * g.z;
  o.w = (v.w - mean) * rstd * g.w;
  ((float4*)(outBase + row * D_))[t] = o;
}

// ---------------------------------------------------------------------------
__global__ __launch_bounds__(256) void softmax_kernel(float* __restrict__ attn) {
  __shared__ float red[8];
  size_t row = blockIdx.x;
  int t = threadIdx.x;
  float4* p = (float4*)(attn + row * (size_t)T_);

  float4 v[4];
#pragma unroll
  for (int i = 0; i < 4; i++) v[i] = p[t + i * 256];

  float m = -3.4e38f;
#pragma unroll
  for (int i = 0; i < 4; i++)
    m = fmaxf(m, fmaxf(fmaxf(v[i].x, v[i].y), fmaxf(v[i].z, v[i].w)));
  m = warpMax(m);
  int w = t >> 5, l = t & 31;
  if (l == 0) red[w] = m;
  __syncthreads();
  if (t < 32) {
    float a = (l < 8) ? red[l] : -3.4e38f;
    a = warpMax(a);
    if (l == 0) red[0] = a;
  }
  __syncthreads();
  m = red[0];
  __syncthreads();

  float s = 0.0f;
#pragma unroll
  for (int i = 0; i < 4; i++) {
    v[i].x = __expf(v[i].x - m);
    v[i].y = __expf(v[i].y - m);
    v[i].z = __expf(v[i].z - m);
    v[i].w = __expf(v[i].w - m);
    s += v[i].x + v[i].y + v[i].z + v[i].w;
  }
  s = warpSum(s);
  if (l == 0) red[w] = s;
  __syncthreads();
  if (t < 32) {
    float a = (l < 8) ? red[l] : 0.0f;
    a = warpSum(a);
    if (l == 0) red[0] = a;
  }
  __syncthreads();
  float inv = 1.0f / red[0];
#pragma unroll
  for (int i = 0; i < 4; i++) {
    v[i].x *= inv; v[i].y *= inv; v[i].z *= inv; v[i].w *= inv;
    p[t + i * 256] = v[i];
  }
}

// ---------------------------------------------------------------------------
// fp32 FFMA GEMM: k = x_n @ W_kv[:, :128]
// ---------------------------------------------------------------------------
#define BM 128
#define BN 128
#define BK 16
#define TM 8
#define TN 8

__global__ __launch_bounds__(256) void kproj_kernel(const float* __restrict__ W) {
  const float* A  = g_xn + (size_t)blockIdx.y * BM * D_;   // lda = D_
  const float* Bm = W;                                     // ldb = 256
  float* C        = g_k + (size_t)blockIdx.y * BM * DH_;   // ldc = DH_
  const int K = D_;

  __shared__ float As[BK][BM];
  __shared__ float Bs[BK][BN];

  int tid = threadIdx.x;
  int tx = tid & 15, ty = tid >> 4;

  float acc[TM][TN];
#pragma unroll
  for (int r = 0; r < TM; r++)
#pragma unroll
    for (int c = 0; c < TN; c++) acc[r][c] = 0.0f;

  const int ar = tid >> 1;
  const int ac = (tid & 1) * 8;
  const int bnr = tid >> 4;
  const int bnc = (tid & 15) * 4;

  for (int kt = 0; kt < K; kt += BK) {
    {
      float4 a0 = *(const float4*)(A + (size_t)ar * D_ + kt + ac);
      float4 a1 = *(const float4*)(A + (size_t)ar * D_ + kt + ac + 4);
      As[ac + 0][ar] = a0.x; As[ac + 1][ar] = a0.y;
      As[ac + 2][ar] = a0.z; As[ac + 3][ar] = a0.w;
      As[ac + 4][ar] = a1.x; As[ac + 5][ar] = a1.y;
      As[ac + 6][ar] = a1.z; As[ac + 7][ar] = a1.w;
    }
    {
      // W_kv rows (stride 256); only cols [0,128) used.
      float4 b0 = *(const float4*)(Bm + (size_t)(kt + bnr) * 256 + bnc);
      float4 b1 = *(const float4*)(Bm + (size_t)(kt + bnr) * 256 + bnc + 64);
      *(float4*)&Bs[bnr][bnc]      = b0;
      *(float4*)&Bs[bnr][bnc + 64] = b1;
    }
    __syncthreads();

#pragma unroll
    for (int kk = 0; kk < BK; kk++) {
      float a[TM], b[TN];
      *(float4*)&a[0] = *(const float4*)&As[kk][ty * TM];
      *(float4*)&a[4] = *(const float4*)&As[kk][ty * TM + 4];
      *(float4*)&b[0] = *(const float4*)&Bs[kk][tx * TN];
      *(float4*)&b[4] = *(const float4*)&Bs[kk][tx * TN + 4];
#pragma unroll
      for (int r = 0; r < TM; r++)
#pragma unroll
        for (int c = 0; c < TN; c++) acc[r][c] += a[r] * b[c];
    }
    __syncthreads();
  }

#pragma unroll
  for (int r = 0; r < TM; r++) {
    float* crow = C + (size_t)(ty * TM + r) * DH_ + tx * TN;
    *(float4*)crow       = make_float4(acc[r][0], acc[r][1], acc[r][2], acc[r][3]);
    *(float4*)(crow + 4) = make_float4(acc[r][4], acc[r][5], acc[r][6], acc[r][7]);
  }
}

// ---------------------------------------------------------------------------
// tf32 helpers
// ---------------------------------------------------------------------------
#define APAD 20     // row stride (floats) for [row][k] tiles: conflict-free
#define BPAD 136    // row stride for [k][n] tiles (out-GEMM B)

__device__ __forceinline__ void cp16(uint32_t dst, const float* src) {
  asm volatile("cp.async.cg.shared.global [%0], [%1], 16;\n" :: "r"(dst), "l"(src));
}
__device__ __forceinline__ uint32_t tf32rna(float f) {
  uint32_t u;
  asm("cvt.rna.tf32.f32 %0, %1;\n" : "=r"(u) : "f"(f));
  return u;
}

#define MMA_TF32(acc, af, bf)                                              \
  asm volatile(                                                            \
      "mma.sync.aligned.m16n8k8.row.col.f32.tf32.tf32.f32 "                \
      "{%0,%1,%2,%3}, {%4,%5,%6,%7}, {%8,%9}, {%0,%1,%2,%3};\n"            \
      : "+f"((acc)[0]), "+f"((acc)[1]), "+f"((acc)[2]), "+f"((acc)[3])     \
      : "r"((af)[0]), "r"((af)[1]), "r"((af)[2]), "r"((af)[3]),            \
        "r"((bf)[0]), "r"((bf)[1]))

// ---------------------------------------------------------------------------
// tf32 sim GEMM: sim = q_n @ k^T   (NT; both operands k-contiguous)
// Per b: M=2048 (h,i), N=4096 (keys), K=128. Block 128x128, BK=16, NIT=8.
// grid (32, 16, 16), 256 threads, 8 warps of 64x32.
// ---------------------------------------------------------------------------
__global__ __launch_bounds__(256) void sim_gemm_tf32(float* __restrict__ attn) {
  __shared__ float As[2][128][APAD];   // [m][k]
  __shared__ float Bs[2][128][APAD];   // [n][k]  (NT: same layout as A)

  const int bx = blockIdx.x, by = blockIdx.y, b = blockIdx.z;
  const int h = by >> 1;
  const int i0 = (by & 1) * 128;
  const float* A  = g_qn + (size_t)b * (N_ * D_) + (size_t)i0 * D_ + h * DH_; // lda=D_
  const float* Bm = g_k  + (size_t)b * (T_ * DH_) + (size_t)bx * 128 * DH_;   // ldb=DH_
  float* C = attn + ((size_t)b * 2048 + (size_t)by * 128) * T_ + (size_t)bx * 128;
  const int ldc = T_;

  const int tid  = threadIdx.x;
  const int lane = tid & 31;
  const int wid  = tid >> 5;
  const int m0 = (wid >> 2) * 64;
  const int n0 = (wid & 3) * 32;

  const int arow = tid >> 1;               // 0..127
  const int acol = (tid & 1) * 8;          // 0 or 8

  uint32_t aBase[2], bBase[2];
#pragma unroll
  for (int s = 0; s < 2; s++) {
    aBase[s] = (uint32_t)__cvta_generic_to_shared(&As[s][arow][acol]);
    bBase[s] = (uint32_t)__cvta_generic_to_shared(&Bs[s][arow][acol]);
  }

  float acc[4][4][4];
#pragma unroll
  for (int i = 0; i < 4; i++)
#pragma unroll
    for (int j = 0; j < 4; j++)
#pragma unroll
      for (int r = 0; r < 4; r++) acc[i][j][r] = 0.0f;

  const int NIT = DH_ / 16;                // 8

  {
    const float* as = A + (size_t)arow * D_ + acol;
    const float* bs = Bm + (size_t)arow * DH_ + acol;
    cp16(aBase[0], as);
    cp16(aBase[0] + 16, as + 4);
    cp16(bBase[0], bs);
    cp16(bBase[0] + 16, bs + 4);
    asm volatile("cp.async.commit_group;\n");
  }

  int buf = 0;
  for (int it = 0; it < NIT; it++) {
    const bool hasNext = (it + 1 < NIT);
    if (hasNext) {
      const int kt = (it + 1) * 16;
      const float* as = A + (size_t)arow * D_ + kt + acol;
      const float* bs = Bm + (size_t)arow * DH_ + kt + acol;
      const int nb = buf ^ 1;
      cp16(aBase[nb], as);
      cp16(aBase[nb] + 16, as + 4);
      cp16(bBase[nb], bs);
      cp16(bBase[nb] + 16, bs + 4);
      asm volatile("cp.async.commit_group;\n");
      asm volatile("cp.async.wait_group 1;\n");
    } else {
      asm volatile("cp.async.wait_group 0;\n");
    }
    __syncthreads();

#pragma unroll
    for (int ks = 0; ks < 16; ks += 8) {
      uint32_t af[4][4];
#pragma unroll
      for (int mf = 0; mf < 4; mf++) {
        int m = m0 + mf * 16 + (lane >> 2);
        int k = ks + (lane & 3);
        af[mf][0] = tf32rna(As[buf][m][k]);
        af[mf][1] = tf32rna(As[buf][m + 8][k]);
        af[mf][2] = tf32rna(As[buf][m][k + 4]);
        af[mf][3] = tf32rna(As[buf][m + 8][k + 4]);
      }
      uint32_t bf[4][2];
#pragma unroll
      for (int nf = 0; nf < 4; nf++) {
        int n = n0 + nf * 8 + (lane >> 2);
        int k = ks + (lane & 3);
        bf[nf][0] = tf32rna(Bs[buf][n][k]);
        bf[nf][1] = tf32rna(Bs[buf][n][k + 4]);
      }
#pragma unroll
      for (int mf = 0; mf < 4; mf++)
#pragma unroll
        for (int nf = 0; nf < 4; nf++) MMA_TF32(acc[mf][nf], af[mf], bf[nf]);
    }
    __syncthreads();
    buf ^= 1;
  }

#pragma unroll
  for (int mf = 0; mf < 4; mf++) {
#pragma unroll
    for (int nf = 0; nf < 4; nf++) {
      int r = m0 + mf * 16 + (lane >> 2);
      int c = n0 + nf * 8 + (lane & 3) * 2;
      float2 v0 = make_float2(acc[mf][nf][0], acc[mf][nf][1]);
      float2 v1 = make_float2(acc[mf][nf][2], acc[mf][nf][3]);
      *(float2*)(C + (size_t)r * ldc + c)       = v0;
      *(float2*)(C + (size_t)(r + 8) * ldc + c) = v1;
    }
  }
}

// ---------------------------------------------------------------------------
// tf32 out GEMM: out = attn @ x_n (NN). Per (b,h): M=256, N=1024, K=4096.
// Block 128x128, BK=16, NIT=256, grid (8, 2, 128), 256 threads.
// ---------------------------------------------------------------------------
__global__ __launch_bounds__(256) void out_gemm_tf32(const float* __restrict__ attn,
                                                     float* __restrict__ out) {
  __shared__ float As[2][128][APAD];   // [m][k]
  __shared__ float Bs[2][16][BPAD];    // [k][n]

  const int bx = blockIdx.x, by = blockIdx.y, bz = blockIdx.z;
  const int b = bz >> 3, h = bz & 7;
  const float* A  = attn + ((size_t)bz * N_ + (size_t)by * 128) * T_;      // lda=T_
  const float* Bm = g_xn + (size_t)b * (T_ * D_) + (size_t)bx * 128;       // ldb=D_
  float* C = out + (size_t)b * (N_ * H_ * D_) + (size_t)by * 128 * (H_ * D_)
                 + (size_t)h * D_ + (size_t)bx * 128;
  const int ldc = H_ * D_;

  const int tid  = threadIdx.x;
  const int lane = tid & 31;
  const int wid  = tid >> 5;
  const int m0 = (wid >> 2) * 64;
  const int n0 = (wid & 3) * 32;

  const int arow = tid >> 1;
  const int acol = (tid & 1) * 8;
  const int bk   = tid >> 4;
  const int bn   = (tid & 15) * 8;

  uint32_t aBase[2], bBase[2];
#pragma unroll
  for (int s = 0; s < 2; s++) {
    aBase[s] = (uint32_t)__cvta_generic_to_shared(&As[s][arow][acol]);
    bBase[s] = (uint32_t)__cvta_generic_to_shared(&Bs[s][bk][bn]);
  }

  float acc[4][4][4];
#pragma unroll
  for (int i = 0; i < 4; i++)
#pragma unroll
    for (int j = 0; j < 4; j++)
#pragma unroll
      for (int r = 0; r < 4; r++) acc[i][j][r] = 0.0f;

  const int NIT = T_ / 16;                 // 256

  {
    const float* as = A + (size_t)arow * T_ + acol;
    const float* bs = Bm + (size_t)bk * D_ + bn;
    cp16(aBase[0], as);
    cp16(aBase[0] + 16, as + 4);
    cp16(bBase[0], bs);
    cp16(bBase[0] + 16, bs + 4);
    asm volatile("cp.async.commit_group;\n");
  }

  int buf = 0;
  for (int it = 0; it < NIT; it++) {
    const bool hasNext = (it + 1 < NIT);
    if (hasNext) {
      const int kt = (it + 1) * 16;
      const float* as = A + (size_t)arow * T_ + kt + acol;
      const float* bs = Bm + (size_t)(kt + bk) * D_ + bn;
      const int nb = buf ^ 1;
      cp16(aBase[nb], as);
      cp16(aBase[nb] + 16, as + 4);
      cp16(bBase[nb], bs);
      cp16(bBase[nb] + 16, bs + 4);
      asm volatile("cp.async.commit_group;\n");
      asm volatile("cp.async.wait_group 1;\n");
    } else {
      asm volatile("cp.async.wait_group 0;\n");
    }
    __syncthreads();

#pragma unroll
    for (int ks = 0; ks < 16; ks += 8) {
      uint32_t af[4][4];
#pragma unroll
      for (int mf = 0; mf < 4; mf++) {
        int m = m0 + mf * 16 + (lane >> 2);
        int k = ks + (lane & 3);
        af[mf][0] = tf32rna(As[buf][m][k]);
        af[mf][1] = tf32rna(As[buf][m + 8][k]);
        af[mf][2] = tf32rna(As[buf][m][k + 4]);
        af[mf][3] = tf32rna(As[buf][m + 8][k + 4]);
      }
      uint32_t bf[4][2];
#pragma unroll
      for (int nf = 0; nf < 4; nf++) {
        int n = n0 + nf * 8 + (lane >> 2);
        int k = ks + (lane & 3);
        bf[nf][0] = tf32rna(Bs[buf][k][n]);
        bf[nf][1] = tf32rna(Bs[buf][k + 4][n]);
      }
#pragma unroll
      for (int mf = 0; mf < 4; mf++)
#pragma unroll
        for (int nf = 0; nf < 4; nf++) MMA_TF32(acc[mf][nf], af[mf], bf[nf]);
    }
    __syncthreads();
    buf ^= 1;
  }

#pragma unroll
  for (int mf = 0; mf < 4; mf++) {
#pragma unroll
    for (int nf = 0; nf < 4; nf++) {
      int r = m0 + mf * 16 + (lane >> 2);
      int c = n0 + nf * 8 + (lane & 3) * 2;
      float2 v0 = make_float2(acc[mf][nf][0], acc[mf][nf][1]);
      float2 v1 = make_float2(acc[mf][nf][2], acc[mf][nf][3]);
      *(float2*)(C + (size_t)r * ldc + c)       = v0;
      *(float2*)(C + (size_t)(r + 8) * ldc + c) = v1;
    }
  }
}

// ---------------------------------------------------------------------------
extern "C" void kernel_launch(void* const* d_in, const int* in_sizes, int n_in,
                              void* d_out, int out_size) {
  (void)in_sizes; (void)n_in; (void)out_size;
  const float* imgq = (const float*)d_in[0];
  const float* x    = (const float*)d_in[1];
  const float* gq   = (const float*)d_in[2];
  const float* gx   = (const float*)d_in[3];
  const float* wkv  = (const float*)d_in[4];

  float* out  = (float*)d_out;
  float* attn = out + OUT_ELEMS;

  const float scale = 0.08838834764831845f;

  ln_kernel<<<B_ * T_, 256>>>(x, gx, 1.0f, 0);
  ln_kernel<<<B_ * N_, 256>>>(imgq, gq, scale, 1);

  kproj_kernel<<<dim3(1, 512), 256>>>(wkv);

  sim_gemm_tf32<<<dim3(32, 16, 16), 256>>>(attn);

  softmax_kernel<<<B_ * H_ * N_, 256>>>(attn);

  out_gemm_tf32<<<dim3(8, 2, 128), 256>>>(attn, out);
}